// round 7
// baseline (speedup 1.0000x reference)
#include <cuda_runtime.h>
#include <cstdint>

// ---------------------------------------------------------------------------
// PositionRelationEncodeUnit_GCN — fused GB300 implementation
//
// Decomposition (N=512, D_OBJ=256, D_BOX=128, D_IN=640, HID=256, D_OUT=256):
//   h[i,j,:]  = A1[i,:] + B1[j,:] + bbox[i,j,:] @ w1c^T        (w1 split 256/256/128)
//   logit[i,j]= c0 + sum_h u[h]*leaky(h[i,j,h])                (BN+w2 folded affine)
//   conf      = renorm(mask * softmax_j(logit))
//   g[i,j,:]  = relu(Ac[i,:] + Bc[j,:] + bbox[i,j,:] @ cw1c^T)
//   G[i,:]    = sum_j conf[i,j]*g[i,j,:]
//   out[i,:]  = G[i,:] @ cw2^T + cb2 * sum_j conf[i,j]
// ---------------------------------------------------------------------------

#define NN   512
#define HID  256
#define DB   128

// ----- device scratch (no allocations allowed) -----
__device__ __align__(16) float g_A1[NN * HID];
__device__ __align__(16) float g_B1[NN * HID];
__device__ __align__(16) float g_Ac[NN * HID];
__device__ __align__(16) float g_Bc[NN * HID];
__device__ __align__(16) float g_w1cT[DB * HID];   // [k][h]
__device__ __align__(16) float g_cw1cT[DB * HID];  // [k][h]
__device__ float g_u[HID];
__device__ float g_c0;
__device__ __align__(16) float g_logits[NN * NN];
__device__ __align__(16) float g_conf[NN * NN];
__device__ float g_ssum[NN];
__device__ __align__(16) float g_Gpart[8 * NN * HID];
__device__ __align__(16) float g_G[NN * HID];

// ----- packed fp32x2 helpers (Blackwell dual-fp32 path) -----
__device__ __forceinline__ unsigned long long pk(float a, float b) {
    unsigned long long r;
    asm("mov.b64 %0, {%1, %2};" : "=l"(r) : "f"(a), "f"(b));
    return r;
}
__device__ __forceinline__ void fma2(unsigned long long& d, unsigned long long a,
                                     unsigned long long b) {
    asm("fma.rn.f32x2 %0, %1, %2, %0;" : "+l"(d) : "l"(a), "l"(b));
}
__device__ __forceinline__ float2 upk(unsigned long long v) {
    float2 f;
    asm("mov.b64 {%0, %1}, %2;" : "=f"(f.x), "=f"(f.y) : "l"(v));
    return f;
}

// ---------------------------------------------------------------------------
// Precompute A1/B1/Ac/Bc :   A1[i,h] = obj[i,:]·w1[h,0:256] + b1[h]
//                            B1[j,h] = obj[j,:]·w1[h,256:512]
//                            Ac,Bc   = same with cw1/cb1
// grid 128 (4 rows each), block 256 (h)
// ---------------------------------------------------------------------------
__global__ void __launch_bounds__(256) k_rowmlp(const float* __restrict__ obj,
                                                const float* __restrict__ w1,
                                                const float* __restrict__ b1,
                                                const float* __restrict__ cw1,
                                                const float* __restrict__ cb1) {
    __shared__ float s_obj[4 * 256];
    const int i0 = blockIdx.x * 4;
    const int tid = threadIdx.x;
#pragma unroll
    for (int r = 0; r < 4; ++r) s_obj[r * 256 + tid] = obj[(i0 + r) * 256 + tid];
    __syncthreads();

    const int h = tid;
    float aA[4] = {0.f, 0.f, 0.f, 0.f}, aB[4] = {0.f, 0.f, 0.f, 0.f};
    float aC[4] = {0.f, 0.f, 0.f, 0.f}, aD[4] = {0.f, 0.f, 0.f, 0.f};
    const float4* wr = (const float4*)(w1 + (size_t)h * 640);
    const float4* cr = (const float4*)(cw1 + (size_t)h * 640);
#pragma unroll 4
    for (int k4 = 0; k4 < 64; ++k4) {
        float4 wa = wr[k4], wb = wr[64 + k4];
        float4 ca = cr[k4], cb = cr[64 + k4];
#pragma unroll
        for (int r = 0; r < 4; ++r) {
            const float* o = s_obj + r * 256 + k4 * 4;
            float o0 = o[0], o1 = o[1], o2 = o[2], o3 = o[3];
            aA[r] += wa.x * o0 + wa.y * o1 + wa.z * o2 + wa.w * o3;
            aB[r] += wb.x * o0 + wb.y * o1 + wb.z * o2 + wb.w * o3;
            aC[r] += ca.x * o0 + ca.y * o1 + ca.z * o2 + ca.w * o3;
            aD[r] += cb.x * o0 + cb.y * o1 + cb.z * o2 + cb.w * o3;
        }
    }
    const float bb1 = b1[h], bcb1 = cb1[h];
#pragma unroll
    for (int r = 0; r < 4; ++r) {
        g_A1[(i0 + r) * 256 + h] = aA[r] + bb1;
        g_B1[(i0 + r) * 256 + h] = aB[r];
        g_Ac[(i0 + r) * 256 + h] = aC[r] + bcb1;
        g_Bc[(i0 + r) * 256 + h] = aD[r];
    }
}

// Transpose the bbox-blocks of w1/cw1 to k-major. grid 128 (k), block 256 (h)
__global__ void k_wtrans(const float* __restrict__ w1, const float* __restrict__ cw1) {
    const int k = blockIdx.x, h = threadIdx.x;
    g_w1cT[k * 256 + h]  = w1[(size_t)h * 640 + 512 + k];
    g_cw1cT[k * 256 + h] = cw1[(size_t)h * 640 + 512 + k];
}

// Fold BN+w2 into (u, c0). single block of 256
__global__ void k_uc0(const float* __restrict__ gamma, const float* __restrict__ beta,
                      const float* __restrict__ mean, const float* __restrict__ var,
                      const float* __restrict__ w2, const float* __restrict__ b2) {
    const int h = threadIdx.x;
    float rs = rsqrtf(var[h] + 1e-5f);
    float sc = gamma[h] * rs;
    g_u[h] = sc * w2[h];
    float t = (beta[h] - mean[h] * sc) * w2[h];
    __shared__ float sr[256];
    sr[h] = t;
    __syncthreads();
    for (int s = 128; s > 0; s >>= 1) {
        if (h < s) sr[h] += sr[h + s];
        __syncthreads();
    }
    if (h == 0) g_c0 = sr[0] + b2[0];
}

// ---------------------------------------------------------------------------
// Shared mainloop: per block computes acc[p][h] = bbox[i, j0+p, :] @ wT[:, h]
// tile: 64 pairs x 256 h, BK=16, 256 threads, thread = 8 pairs x 8 h
// acc layout: acc[pp*4+hh] = f32x2 pair of h-values
//   pair(pp) = pp<4 ? 4*ty+pp : 32+4*ty+(pp-4)
//   h(hh)    = (hh>=2?128:0) + 4*tx + (hh&1)*2  (covers that h and h+1)
// ---------------------------------------------------------------------------
__device__ __forceinline__ void pair_gemm(const float* __restrict__ bb,
                                          const float* __restrict__ wT,
                                          float* s_w, float* s_bb,
                                          unsigned long long* acc,
                                          int tid, int tx, int ty) {
#pragma unroll 1
    for (int kt = 0; kt < 8; ++kt) {
        __syncthreads();
        // stage weights: 16x256 floats, k-major (contiguous, coalesced)
        const float4* wsrc = (const float4*)(wT + kt * 16 * 256);
        float4* wdst = (float4*)s_w;
#pragma unroll
        for (int q = 0; q < 4; ++q) wdst[q * 256 + tid] = wsrc[q * 256 + tid];
        // stage bbox transposed: s_bb[k][p], rows padded to 68 (16B-aligned)
        {
            const int p = tid >> 2, q = tid & 3;
            float4 v = *(const float4*)(bb + (size_t)p * 128 + kt * 16 + q * 4);
            s_bb[(q * 4 + 0) * 68 + p] = v.x;
            s_bb[(q * 4 + 1) * 68 + p] = v.y;
            s_bb[(q * 4 + 2) * 68 + p] = v.z;
            s_bb[(q * 4 + 3) * 68 + p] = v.w;
        }
        __syncthreads();
#pragma unroll
        for (int k = 0; k < 16; ++k) {
            float4 b0 = *(const float4*)(s_bb + k * 68 + 4 * ty);
            float4 b1v = *(const float4*)(s_bb + k * 68 + 32 + 4 * ty);
            float4 w0 = *(const float4*)(s_w + k * 256 + 4 * tx);
            float4 w1v = *(const float4*)(s_w + k * 256 + 128 + 4 * tx);
            unsigned long long wp0 = pk(w0.x, w0.y), wp1 = pk(w0.z, w0.w);
            unsigned long long wp2 = pk(w1v.x, w1v.y), wp3 = pk(w1v.z, w1v.w);
            float bf[8] = {b0.x, b0.y, b0.z, b0.w, b1v.x, b1v.y, b1v.z, b1v.w};
#pragma unroll
            for (int pp = 0; pp < 8; ++pp) {
                unsigned long long bp = pk(bf[pp], bf[pp]);
                fma2(acc[pp * 4 + 0], bp, wp0);
                fma2(acc[pp * 4 + 1], bp, wp1);
                fma2(acc[pp * 4 + 2], bp, wp2);
                fma2(acc[pp * 4 + 3], bp, wp3);
            }
        }
    }
}

// ---------------------------------------------------------------------------
// Pass 1: logits[i,j] = c0 + sum_h u[h]*leaky(acc + A1[i,h] + B1[j,h])
// grid (8, 512): jt, i
// ---------------------------------------------------------------------------
__global__ void __launch_bounds__(256) k_pass1(const float* __restrict__ bbox) {
    __shared__ __align__(16) float s_w[16 * 256];
    __shared__ __align__(16) float s_bb[16 * 68];
    __shared__ float s_a1[256];
    __shared__ float s_u[256];

    const int jt = blockIdx.x, i = blockIdx.y;
    const int j0 = jt * 64;
    const int tid = threadIdx.x, tx = tid & 31, ty = tid >> 5;

    s_a1[tid] = g_A1[i * 256 + tid];
    s_u[tid] = g_u[tid];

    unsigned long long acc[32];
#pragma unroll
    for (int q = 0; q < 32; ++q) acc[q] = 0ull;

    const float* bb = bbox + ((size_t)i * NN + j0) * DB;
    pair_gemm(bb, g_w1cT, s_w, s_bb, acc, tid, tx, ty);

    const float c0 = g_c0;
#pragma unroll
    for (int pp = 0; pp < 8; ++pp) {
        const int p = (pp < 4) ? (4 * ty + pp) : (32 + 4 * ty + (pp - 4));
        const float* b1row = g_B1 + (size_t)(j0 + p) * 256;
        float s = 0.f;
#pragma unroll
        for (int hh = 0; hh < 4; ++hh) {
            const int hb = ((hh >> 1) * 128) + 4 * tx + (hh & 1) * 2;
            float2 v = upk(acc[pp * 4 + hh]);
            float2 bv = *(const float2*)(b1row + hb);
            float x = v.x + s_a1[hb] + bv.x;
            x = x > 0.f ? x : 0.01f * x;
            float y = v.y + s_a1[hb + 1] + bv.y;
            y = y > 0.f ? y : 0.01f * y;
            s += s_u[hb] * x + s_u[hb + 1] * y;
        }
#pragma unroll
        for (int off = 16; off > 0; off >>= 1)
            s += __shfl_xor_sync(0xffffffffu, s, off);
        if (tx == 0) g_logits[i * NN + j0 + p] = s + c0;
    }
}

// ---------------------------------------------------------------------------
// Softmax + mask renorm per row. grid 512, block 256 (2 cols/thread)
// conf = e*m / (sum(e*m) + 1e-8*sum(e));  ssum = sum(e*m)/(same denom)
// ---------------------------------------------------------------------------
__global__ void k_conf(const float* __restrict__ mask) {
    const int i = blockIdx.x, tid = threadIdx.x;
    __shared__ float sr[256];
    float l0 = g_logits[i * NN + tid];
    float l1 = g_logits[i * NN + 256 + tid];

    sr[tid] = fmaxf(l0, l1);
    __syncthreads();
    for (int s = 128; s > 0; s >>= 1) {
        if (tid < s) sr[tid] = fmaxf(sr[tid], sr[tid + s]);
        __syncthreads();
    }
    const float m = sr[0];
    __syncthreads();

    float e0 = __expf(l0 - m), e1 = __expf(l1 - m);
    sr[tid] = e0 + e1;
    __syncthreads();
    for (int s = 128; s > 0; s >>= 1) {
        if (tid < s) sr[tid] += sr[tid + s];
        __syncthreads();
    }
    const float E = sr[0];
    __syncthreads();

    float m0 = mask[i * NN + tid], m1 = mask[i * NN + 256 + tid];
    float em0 = e0 * m0, em1 = e1 * m1;
    sr[tid] = em0 + em1;
    __syncthreads();
    for (int s = 128; s > 0; s >>= 1) {
        if (tid < s) sr[tid] += sr[tid + s];
        __syncthreads();
    }
    const float EM = sr[0];
    const float inv = 1.f / (EM + 1e-8f * E);
    g_conf[i * NN + tid] = em0 * inv;
    g_conf[i * NN + 256 + tid] = em1 * inv;
    if (tid == 0) g_ssum[i] = EM * inv;
}

// ---------------------------------------------------------------------------
// Pass 2: Gpart[jt,i,h] = sum_{p in tile} conf[i,j0+p]*relu(acc + Ac[i,h] + Bc[j,h])
// grid (8, 512)
// ---------------------------------------------------------------------------
__global__ void __launch_bounds__(256) k_pass2(const float* __restrict__ bbox) {
    __shared__ __align__(16) float s_w[16 * 256];
    __shared__ __align__(16) float s_bb[16 * 68];
    __shared__ float s_ac[256];
    __shared__ float s_red[8 * 256];

    const int jt = blockIdx.x, i = blockIdx.y;
    const int j0 = jt * 64;
    const int tid = threadIdx.x, tx = tid & 31, ty = tid >> 5;

    s_ac[tid] = g_Ac[i * 256 + tid];

    unsigned long long acc[32];
#pragma unroll
    for (int q = 0; q < 32; ++q) acc[q] = 0ull;

    const float* bb = bbox + ((size_t)i * NN + j0) * DB;
    pair_gemm(bb, g_cw1cT, s_w, s_bb, acc, tid, tx, ty);

    float hs[8];
#pragma unroll
    for (int q = 0; q < 8; ++q) hs[q] = 0.f;

#pragma unroll
    for (int pp = 0; pp < 8; ++pp) {
        const int p = (pp < 4) ? (4 * ty + pp) : (32 + 4 * ty + (pp - 4));
        const float c = g_conf[i * NN + j0 + p];
        const float* bcrow = g_Bc + (size_t)(j0 + p) * 256;
#pragma unroll
        for (int hh = 0; hh < 4; ++hh) {
            const int hb = ((hh >> 1) * 128) + 4 * tx + (hh & 1) * 2;
            float2 v = upk(acc[pp * 4 + hh]);
            float2 bv = *(const float2*)(bcrow + hb);
            float x = fmaxf(v.x + s_ac[hb] + bv.x, 0.f);
            float y = fmaxf(v.y + s_ac[hb + 1] + bv.y, 0.f);
            hs[hh * 2 + 0] += c * x;
            hs[hh * 2 + 1] += c * y;
        }
    }
#pragma unroll
    for (int hh = 0; hh < 4; ++hh) {
        const int hb = ((hh >> 1) * 128) + 4 * tx + (hh & 1) * 2;
        s_red[ty * 256 + hb] = hs[hh * 2 + 0];
        s_red[ty * 256 + hb + 1] = hs[hh * 2 + 1];
    }
    __syncthreads();
    const int h = tid;
    float s = 0.f;
#pragma unroll
    for (int w = 0; w < 8; ++w) s += s_red[w * 256 + h];
    g_Gpart[((size_t)jt * NN + i) * 256 + h] = s;
}

// Reduce the 8 j-tile partials. grid 512 (i), block 256 (h)
__global__ void k_reduceG() {
    const int i = blockIdx.x, h = threadIdx.x;
    float s = 0.f;
#pragma unroll
    for (int c = 0; c < 8; ++c) s += g_Gpart[((size_t)c * NN + i) * 256 + h];
    g_G[i * 256 + h] = s;
}

// Final tiny GEMM: out[i,d] = G[i,:]·cw2[d,:] + cb2[d]*ssum[i]. grid 64 (8 i each)
__global__ void __launch_bounds__(256) k_final(const float* __restrict__ cw2,
                                               const float* __restrict__ cb2,
                                               float* __restrict__ out) {
    __shared__ float s_G[8 * 256];
    const int i0 = blockIdx.x * 8;
    const int tid = threadIdx.x;
#pragma unroll
    for (int r = 0; r < 8; ++r) s_G[r * 256 + tid] = g_G[(i0 + r) * 256 + tid];
    __syncthreads();

    const int d = tid;
    float acc[8];
#pragma unroll
    for (int r = 0; r < 8; ++r) acc[r] = 0.f;
    const float4* wr = (const float4*)(cw2 + (size_t)d * 256);
#pragma unroll 4
    for (int k4 = 0; k4 < 64; ++k4) {
        float4 w = wr[k4];
#pragma unroll
        for (int r = 0; r < 8; ++r) {
            const float* g = s_G + r * 256 + k4 * 4;
            acc[r] += w.x * g[0] + w.y * g[1] + w.z * g[2] + w.w * g[3];
        }
    }
    const float cb = cb2[d];
#pragma unroll
    for (int r = 0; r < 8; ++r)
        out[(i0 + r) * 256 + d] = acc[r] + cb * g_ssum[i0 + r];
}

// ---------------------------------------------------------------------------
extern "C" void kernel_launch(void* const* d_in, const int* in_sizes, int n_in,
                              void* d_out, int out_size) {
    (void)in_sizes; (void)n_in; (void)out_size;
    const float* obj   = (const float*)d_in[0];
    const float* bbox  = (const float*)d_in[1];
    const float* mask  = (const float*)d_in[2];
    const float* w1    = (const float*)d_in[3];
    const float* b1    = (const float*)d_in[4];
    const float* gamma = (const float*)d_in[5];
    const float* beta  = (const float*)d_in[6];
    const float* mean  = (const float*)d_in[7];
    const float* var   = (const float*)d_in[8];
    const float* w2    = (const float*)d_in[9];
    const float* b2    = (const float*)d_in[10];
    const float* cw1   = (const float*)d_in[11];
    const float* cb1   = (const float*)d_in[12];
    const float* cw2   = (const float*)d_in[13];
    const float* cb2   = (const float*)d_in[14];
    float* out = (float*)d_out;

    k_rowmlp<<<128, 256>>>(obj, w1, b1, cw1, cb1);
    k_wtrans<<<128, 256>>>(w1, cw1);
    k_uc0<<<1, 256>>>(gamma, beta, mean, var, w2, b2);
    k_pass1<<<dim3(8, 512), 256>>>(bbox);
    k_conf<<<512, 256>>>(mask);
    k_pass2<<<dim3(8, 512), 256>>>(bbox);
    k_reduceG<<<512, 256>>>();
    k_final<<<64, 256>>>(cw2, cb2, out);
}